// round 9
// baseline (speedup 1.0000x reference)
#include <cuda_runtime.h>

// ---------------- problem constants ----------------
#define VOCABN 35
#define PADV   34
#define HID    256
#define NSEQ   128
#define TT     256
#define TQn    255
#define HB     16           // h-indices per CTA
#define SB     16           // sequences per group
#define NSG    8            // sequence groups = clusters
#define CLSZ   16           // CTAs per cluster (h-blocks)
#define KP     65           // padded row stride in float4 units
#define ROWS7  1792
#define ARRN   (NSEQ*TQn*HID)
#define PSS    464          // partials slot stride (floats); PSS mod 32 == 16 -> conflict-free

// ---------------- device scratch ----------------
__device__ float g_ztab[VOCABN * ROWS7];
__device__ float g_hbuf[2][NSEQ * HID];

__device__ __forceinline__ void ffma2(unsigned long long &d,
                                      unsigned long long a,
                                      unsigned long long b) {
    asm("fma.rn.f32x2 %0, %1, %2, %0;" : "+l"(d) : "l"(a), "l"(b));
}
__device__ __forceinline__ float fsig(float x) {
    float e = __expf(-x);
    return __fdividef(1.0f, 1.0f + e);
}
__device__ __forceinline__ float ftanh_(float x) {
    float e = __expf(2.0f * x);
    return 1.0f - __fdividef(2.0f, e + 1.0f);
}

// ---------------- kernel A: Ztab = Emb @ W_x^T + b ----------------
__global__ void __launch_bounds__(256) ztab_kernel(const float* __restrict__ Emb,
                                                   const float* __restrict__ W,
                                                   const float* __restrict__ bias) {
    __shared__ float4 sE[7 * KP];
    const int t  = threadIdx.x;
    const int rb = blockIdx.x % 7;
    const int vg = blockIdx.x / 7;
    const int v0 = vg * 7;

    for (int f = t; f < 7 * 64; f += 256) {
        int j = f >> 6, kc = f & 63;
        sE[j * KP + kc] = ((const float4*)Emb)[(v0 + j) * 64 + kc];
    }
    __syncthreads();

    const int r = rb * 256 + t;
    float acc[7];
    const float bb = bias[r];
#pragma unroll
    for (int j = 0; j < 7; ++j) acc[j] = bb;

    const float4* wr = ((const float4*)W) + (size_t)r * 128;
#pragma unroll 4
    for (int kc = 0; kc < 64; ++kc) {
        float4 w = wr[kc];
#pragma unroll
        for (int j = 0; j < 7; ++j) {
            float4 e = sE[j * KP + kc];
            acc[j] += w.x * e.x + w.y * e.y + w.z * e.z + w.w * e.w;
        }
    }
#pragma unroll
    for (int j = 0; j < 7; ++j)
        g_ztab[(v0 + j) * ROWS7 + r] = acc[j];
}

// ---------------- kernel B: cluster-synchronized persistent reverse scan ----------------
#define OFF_W   0                                   // 112*KP*16 = 116480
#define OFF_H   (112 * KP * 16)                     // 16*KP*16  =  16640
#define OFF_Z   (OFF_H + 16 * KP * 16)              // 35*112*4  =  15680
#define OFF_PS  (OFF_Z + VOCABN * 112 * 4)          // 16*PSS*4  =  29696
#define OFF_EV  (OFF_PS + 16 * PSS * 4)             // 16*256    =   4096
#define OFF_DT  (OFF_EV + 16 * 256)                 // 16*256*4  =  16384
static const int SMEM_TOTAL = OFF_DT + 16 * 256 * 4;   // 198976 B

__global__ void __launch_bounds__(256, 1) __cluster_dims__(CLSZ, 1, 1)
scan_kernel(const int*   __restrict__ ev,
            const float* __restrict__ dtime,
            const float* __restrict__ W,
            float*       __restrict__ out) {
    extern __shared__ char smem[];
    float4*        sW4 = (float4*)(smem + OFF_W);
    float4*        sH4 = (float4*)(smem + OFF_H);
    float*         sZ  = (float*) (smem + OFF_Z);
    float*         ps  = (float*) (smem + OFF_PS);
    unsigned char* sEv = (unsigned char*)(smem + OFF_EV);
    float*         sDt = (float*) (smem + OFF_DT);

    const int t   = threadIdx.x;
    const int cta = blockIdx.x;
    const int sg  = cta >> 4;        // cluster id = sequence group
    const int g   = cta & 15;        // cluster rank = h-block
    const int q0  = sg * SB;
    const int nb  = t & 15;          // h index within block
    const int sq  = (t >> 4) & 3;    // seq quad
    const int ks  = t >> 6;          // K quarter
    const int s_g = sq * 4 + ks;     // gate-role local sequence
    const int q_g = q0 + s_g;

    // ---- persistent W slice: rows g7*256 + g*16 + j, cols 256..511 ----
    for (int f = t; f < 112 * 64; f += 256) {
        int row = f >> 6, kc = f & 63;
        int g7 = row >> 4, j = row & 15;
        int rg = g7 * HID + g * HB + j;
        sW4[row * KP + kc] = ((const float4*)W)[(size_t)rg * 128 + 64 + kc];
    }
    // ---- persistent Ztab slice ----
    for (int z = t; z < VOCABN * 112; z += 256) {
        int v = z / 112, rl = z % 112;
        int g7 = rl >> 4, j = rl & 15;
        sZ[z] = g_ztab[v * ROWS7 + g7 * HID + g * HB + j];
    }
    // ---- preload event / dtime for this sequence group ----
    for (int f = t; f < 16 * 256; f += 256) {
        int s = f >> 8, i = f & 255;
        sEv[f] = (unsigned char)ev[(q0 + s) * TT + i];
        sDt[f] = dtime[(q0 + s) * TT + i];
    }
    __syncthreads();

    float c_st = 0.0f, cb_st = 0.0f;

    const float4* sWrow = sW4 + nb * KP + ks * 16;
    const float4* sHrow = sH4 + (sq * 4) * KP + ks * 16;
    float* myps = ps + (ks * 4 + sq) * PSS + nb;

    for (int iter = 0; iter < TQn; ++iter) {
        const int tq = TQn - 1 - iter;
        const int i  = tq + 1;

        // ---- stage this group's hidden state into smem ----
        if (iter == 0) {
#pragma unroll
            for (int k = 0; k < 4; ++k) {
                int f = t + k * 256;
                sH4[(f >> 6) * KP + (f & 63)] = make_float4(0.f, 0.f, 0.f, 0.f);
            }
        } else {
            const float4* hsrc = (const float4*)(g_hbuf[iter & 1] + q0 * HID);
            float4 hv[4];
#pragma unroll
            for (int k = 0; k < 4; ++k) hv[k] = __ldcv(hsrc + t + k * 256);  // L2-direct
#pragma unroll
            for (int k = 0; k < 4; ++k) {
                int f = t + k * 256;
                sH4[(f >> 6) * KP + (f & 63)] = hv[k];
            }
        }
        __syncthreads();

        // ---- matvec: 7 gates x 4 seqs, quarter-K (fp32x2 packed FMA) ----
        unsigned long long acc[7][4];
#pragma unroll
        for (int g7 = 0; g7 < 7; ++g7)
#pragma unroll
            for (int sl = 0; sl < 4; ++sl) acc[g7][sl] = 0ULL;

#pragma unroll 4
        for (int kc = 0; kc < 16; ++kc) {
            ulonglong2 h0 = ((const ulonglong2*)(sHrow + 0 * KP))[kc];
            ulonglong2 h1 = ((const ulonglong2*)(sHrow + 1 * KP))[kc];
            ulonglong2 h2 = ((const ulonglong2*)(sHrow + 2 * KP))[kc];
            ulonglong2 h3 = ((const ulonglong2*)(sHrow + 3 * KP))[kc];
#pragma unroll
            for (int g7 = 0; g7 < 7; ++g7) {
                ulonglong2 wv = ((const ulonglong2*)(sWrow + g7 * (16 * KP)))[kc];
                ffma2(acc[g7][0], wv.x, h0.x); ffma2(acc[g7][0], wv.y, h0.y);
                ffma2(acc[g7][1], wv.x, h1.x); ffma2(acc[g7][1], wv.y, h1.y);
                ffma2(acc[g7][2], wv.x, h2.x); ffma2(acc[g7][2], wv.y, h2.y);
                ffma2(acc[g7][3], wv.x, h3.x); ffma2(acc[g7][3], wv.y, h3.y);
            }
        }

        // ---- partials (conflict-free: PSS mod 32 == 16) ----
#pragma unroll
        for (int g7 = 0; g7 < 7; ++g7)
#pragma unroll
            for (int sl = 0; sl < 4; ++sl) {
                float2 p = *(float2*)&acc[g7][sl];
                myps[(sl * 7 + g7) * 16] = p.x + p.y;
            }
        __syncthreads();

        // ---- gate role: reduce 4 K-quarters, add Ztab, cell math ----
        const int   v  = (int)sEv[s_g * 256 + i];
        const float dt = sDt[s_g * 256 + i];

        float za[7];
        const float* zb = sZ + v * 112 + nb;
#pragma unroll
        for (int g7 = 0; g7 < 7; ++g7) {
            float sum = zb[g7 * 16];
#pragma unroll
            for (int kk = 0; kk < 4; ++kk)
                sum += ps[(kk * 4 + sq) * PSS + (ks * 7 + g7) * 16 + nb];
            za[g7] = sum;
        }

        float gi  = fsig(za[0]);
        float gf  = fsig(za[1]);
        float go  = fsig(za[2]);
        float gz  = ftanh_(za[3]);
        float gib = fsig(za[4]);
        float gfb = fsig(za[5]);
        float x6  = za[6];
        float gd  = fmaxf(x6, 0.0f) + log1pf(__expf(-fabsf(x6)));

        float cell   = gf * c_st + gi * gz;
        float cbar   = gfb * cb_st + gib * gz;
        float hminus = go * ftanh_(cell);
        float decay  = __expf(-gd * dt);
        float cnew   = cbar + (cell - cbar) * decay;
        float hnew   = go * ftanh_(cnew);
        float m      = (v != PADV) ? 1.0f : 0.0f;
        cnew *= m;
        float cbarm = cbar * m;
        hnew *= m;
        c_st  = cnew;
        cb_st = cbarm;

        // ---- publish h, arrive (release), overlap output stores, wait ----
        g_hbuf[(iter + 1) & 1][q_g * HID + g * HB + nb] = hnew;
        asm volatile("barrier.cluster.arrive.aligned;" ::: "memory");

        const int ob = (q_g * TQn + tq) * HID + g * HB + nb;
        out[0 * ARRN + ob] = cell;
        out[1 * ARRN + ob] = cbarm;
        out[2 * ARRN + ob] = gd;
        out[3 * ARRN + ob] = go;
        out[4 * ARRN + ob] = hnew;
        out[5 * ARRN + ob] = hminus;

        asm volatile("barrier.cluster.wait.aligned;" ::: "memory");
    }
}

// ---------------- launch ----------------
extern "C" void kernel_launch(void* const* d_in, const int* in_sizes, int n_in,
                              void* d_out, int out_size) {
    const int*   ev    = (const int*)  d_in[0];
    const float* dtime = (const float*)d_in[1];
    const float* Emb   = (const float*)d_in[2];
    const float* W     = (const float*)d_in[3];
    const float* bias  = (const float*)d_in[4];
    float* out = (float*)d_out;

    ztab_kernel<<<35, 256>>>(Emb, W, bias);

    cudaFuncSetAttribute(scan_kernel,
                         cudaFuncAttributeNonPortableClusterSizeAllowed, 1);
    cudaFuncSetAttribute(scan_kernel,
                         cudaFuncAttributeMaxDynamicSharedMemorySize, SMEM_TOTAL);
    scan_kernel<<<128, 256, SMEM_TOTAL>>>(ev, dtime, W, out);
}

// round 12
// speedup vs baseline: 1.2936x; 1.2936x over previous
#include <cuda_runtime.h>

// ---------------- problem constants ----------------
#define VOCABN 35
#define PADV   34
#define HID    256
#define NSEQ   128
#define TT     256
#define TQn    255
#define NSG    8            // sequence groups (16 seqs each)
#define KP     65           // padded row stride in float4 units (64 real + 1)
#define ROWS7  1792
#define ARRN   (NSEQ*TQn*HID)

// decomposition: 128 CTAs = 32 h-blocks (8 h) x 4 group-pairs.
// half-CTA 0 (threads 0-127) runs group 2*gp, half-CTA 1 runs group 2*gp+1.
#define HB2    8            // h per CTA
#define NARR   32           // CTA-halves arriving per group barrier

// partials: per group, addr = slot(ks*4+sq)*PSS + (j*7+g7)*8 + nb
// PSS mod 32 == 8 -> writer banks sq*8+nb all distinct; reader banks distinct.
#define PSS    232
#define PSG    (16*PSS)     // floats per group (3712)

// ---------------- device scratch ----------------
__device__ float    g_ztab[VOCABN * ROWS7];
__device__ float    g_hbuf[2][NSEQ * HID];
__device__ unsigned g_cnt[NSG];                  // central barrier counters (self-resetting)
__device__ unsigned g_gen[NSG];                  // generations (monotonic across replays)

__device__ __forceinline__ void ffma2(unsigned long long &d,
                                      unsigned long long a,
                                      unsigned long long b) {
    asm("fma.rn.f32x2 %0, %1, %2, %0;" : "+l"(d) : "l"(a), "l"(b));
}
__device__ __forceinline__ float fsig(float x) {
    float e = __expf(-x);
    return __fdividef(1.0f, 1.0f + e);
}
__device__ __forceinline__ float ftanh_(float x) {
    float e = __expf(2.0f * x);
    return 1.0f - __fdividef(2.0f, e + 1.0f);
}
#define BARS(id) asm volatile("bar.sync %0, 128;" :: "r"(id) : "memory")

// ---------------- kernel A: Ztab = Emb @ W_x^T + b ----------------
__global__ void __launch_bounds__(256) ztab_kernel(const float* __restrict__ Emb,
                                                   const float* __restrict__ W,
                                                   const float* __restrict__ bias) {
    __shared__ float4 sE[7 * KP];
    const int t  = threadIdx.x;
    const int rb = blockIdx.x % 7;
    const int vg = blockIdx.x / 7;
    const int v0 = vg * 7;

    for (int f = t; f < 7 * 64; f += 256) {
        int j = f >> 6, kc = f & 63;
        sE[j * KP + kc] = ((const float4*)Emb)[(v0 + j) * 64 + kc];
    }
    __syncthreads();

    const int r = rb * 256 + t;
    float acc[7];
    const float bb = bias[r];
#pragma unroll
    for (int j = 0; j < 7; ++j) acc[j] = bb;

    const float4* wr = ((const float4*)W) + (size_t)r * 128;
#pragma unroll 4
    for (int kc = 0; kc < 64; ++kc) {
        float4 w = wr[kc];
#pragma unroll
        for (int j = 0; j < 7; ++j) {
            float4 e = sE[j * KP + kc];
            acc[j] += w.x * e.x + w.y * e.y + w.z * e.z + w.w * e.w;
        }
    }
#pragma unroll
    for (int j = 0; j < 7; ++j)
        g_ztab[(v0 + j) * ROWS7 + r] = acc[j];
}

// ---------------- kernel B: persistent scan, 2 halves + central gen barrier ----------------
#define OFF_W   0                               // 56*KP*16            = 58240
#define OFF_H   (56 * KP * 16)                  // 2 * 16*KP*16        = 33280
#define OFF_Z   (OFF_H + 2 * 16 * KP * 16)      // VOCABN*56*4         =  7840
#define OFF_PS  (OFF_Z + VOCABN * 56 * 4)       // 2 * PSG * 4         = 29696
static const int SMEM_TOTAL = OFF_PS + 2 * PSG * 4;   // 129056 B

__global__ void __launch_bounds__(256, 1)
scan_kernel(const int*   __restrict__ ev,
            const float* __restrict__ dtime,
            const float* __restrict__ W,
            float*       __restrict__ out) {
    extern __shared__ char smem[];
    const float4* sW4 = (const float4*)(smem + OFF_W);
    const float*  sZ  = (const float*) (smem + OFF_Z);

    const int t   = threadIdx.x;
    const int cta = blockIdx.x;
    const int hb  = cta & 31;          // h-block 0..31
    const int gp  = cta >> 5;          // group pair 0..3

    const int hf  = t >> 7;            // half 0: warps 0-3, half 1: warps 4-7
    const int tl  = t & 127;
    const int sg  = gp * 2 + hf;       // this half's sequence group
    const int q0  = sg * 16;
    const int bid = 1 + hf;            // named barrier id

    const int nb = tl & 7;             // h index (compute role)
    const int sq = (tl >> 3) & 3;      // seq quad
    const int ks = tl >> 5;            // K quarter
    const int s  = tl >> 3;            // gate role: sequence 0..15
    const int h  = tl & 7;             // gate role: h 0..7
    const int q  = q0 + s;

    float4* sH4g = (float4*)(smem + OFF_H) + hf * (16 * KP);
    float*  psg  = (float*)(smem + OFF_PS) + hf * PSG;

    // Race-free launch epoch: g_gen[sg] can only advance after ALL 32 halves
    // arrive at g_cnt for iter 0, and every half reads gen0 before its first
    // arrival -> no increment can precede any baseline read.
    const unsigned gen0 = *((volatile unsigned*)&g_gen[sg]);

    // ---- persistent W slice (shared by both halves) ----
    {
        float4* sW4w = (float4*)(smem + OFF_W);
        for (int f = t; f < 56 * 64; f += 256) {
            int row = f >> 6, kc = f & 63;          // row = g7*8 + j
            int g7 = row >> 3, j = row & 7;
            int rg = g7 * HID + hb * HB2 + j;
            sW4w[row * KP + kc] = ((const float4*)W)[(size_t)rg * 128 + 64 + kc];
        }
        float* sZw = (float*)(smem + OFF_Z);
        for (int z = t; z < VOCABN * 56; z += 256) {
            int v = z / 56, rl = z % 56;
            int g7 = rl >> 3, j = rl & 7;
            sZw[z] = g_ztab[v * ROWS7 + g7 * HID + hb * HB2 + j];
        }
    }
    __syncthreads();

    // ---- anti-phase stagger: half B starts ~half a step later (pure delay) ----
    if (hf == 1) {
        long long t0 = clock64();
        while (clock64() - t0 < 3000) { }
    }

    float c_st = 0.0f, cb_st = 0.0f;

    const float4* sWrow = sW4 + nb * KP + ks * 16;
    const float4* sHrow = sH4g + (4 * sq) * KP + ks * 16;
    float* psw = psg + (ks * 4 + sq) * PSS + nb;
    const float* psr = psg + (s >> 2) * PSS + h;

    for (int iter = 0; iter < TQn; ++iter) {
        const int tq = TQn - 1 - iter;
        const int i  = tq + 1;

        // prefetch inputs for gate role (independent of the barrier)
        const int   v   = __ldg(ev    + q * TT + i);
        const float dtv = __ldg(dtime + q * TT + i);

        // ---- acquire: ALL threads spin on the group's generation counter ----
        if (iter > 0) {
            volatile unsigned* genp = (volatile unsigned*)&g_gen[sg];
            while (*genp - gen0 < (unsigned)iter) { }
            __threadfence();   // acquire: order h loads after gen observation

            const float4* hsrc = (const float4*)(g_hbuf[iter & 1] + q0 * HID);
            float4 hv[8];
#pragma unroll
            for (int k = 0; k < 8; ++k) hv[k] = __ldcv(hsrc + tl + k * 128);
#pragma unroll
            for (int k = 0; k < 8; ++k) {
                int f = tl + k * 128;
                sH4g[(f >> 6) * KP + (f & 63)] = hv[k];
            }
        } else {
#pragma unroll
            for (int k = 0; k < 8; ++k) {
                int f = tl + k * 128;
                sH4g[(f >> 6) * KP + (f & 63)] = make_float4(0.f, 0.f, 0.f, 0.f);
            }
        }
        BARS(bid);

        // ---- matvec: 7 gates x 4 seqs, quarter-K (fp32x2) ----
        unsigned long long acc[7][4];
#pragma unroll
        for (int g7 = 0; g7 < 7; ++g7)
#pragma unroll
            for (int j = 0; j < 4; ++j) acc[g7][j] = 0ULL;

#pragma unroll 4
        for (int kc = 0; kc < 16; ++kc) {
            ulonglong2 h0 = ((const ulonglong2*)(sHrow + 0 * KP))[kc];
            ulonglong2 h1 = ((const ulonglong2*)(sHrow + 1 * KP))[kc];
            ulonglong2 h2 = ((const ulonglong2*)(sHrow + 2 * KP))[kc];
            ulonglong2 h3 = ((const ulonglong2*)(sHrow + 3 * KP))[kc];
#pragma unroll
            for (int g7 = 0; g7 < 7; ++g7) {
                ulonglong2 wv = ((const ulonglong2*)(sWrow + g7 * (HB2 * KP)))[kc];
                ffma2(acc[g7][0], wv.x, h0.x); ffma2(acc[g7][0], wv.y, h0.y);
                ffma2(acc[g7][1], wv.x, h1.x); ffma2(acc[g7][1], wv.y, h1.y);
                ffma2(acc[g7][2], wv.x, h2.x); ffma2(acc[g7][2], wv.y, h2.y);
                ffma2(acc[g7][3], wv.x, h3.x); ffma2(acc[g7][3], wv.y, h3.y);
            }
        }

        // ---- partials (conflict-free) ----
#pragma unroll
        for (int g7 = 0; g7 < 7; ++g7)
#pragma unroll
            for (int j = 0; j < 4; ++j) {
                float2 p = *(float2*)&acc[g7][j];
                psw[(j * 7 + g7) * 8] = p.x + p.y;
            }
        BARS(bid);

        // ---- gate role: reduce 4 K-quarters, add Ztab, cell math ----
        float za[7];
#pragma unroll
        for (int g7 = 0; g7 < 7; ++g7) {
            const int bo = ((s & 3) * 7 + g7) * 8;
            float a0 = psr[bo] + psr[bo + 928];
            float a1 = psr[bo + 1856] + psr[bo + 2784];
            za[g7] = sZ[v * 56 + g7 * 8 + h] + (a0 + a1);
        }

        float gi  = fsig(za[0]);
        float gf  = fsig(za[1]);
        float go  = fsig(za[2]);
        float gz  = ftanh_(za[3]);
        float gib = fsig(za[4]);
        float gfb = fsig(za[5]);
        float x6  = za[6];
        float gd  = fmaxf(x6, 0.0f) + log1pf(__expf(-fabsf(x6)));

        float cell   = gf * c_st + gi * gz;
        float cbar   = gfb * cb_st + gib * gz;
        float decay  = __expf(-gd * dtv);
        float cnew   = cbar + (cell - cbar) * decay;
        float hnew   = go * ftanh_(cnew);
        float m      = (v != PADV) ? 1.0f : 0.0f;
        cnew *= m;
        float cbarm = cbar * m;
        hnew *= m;
        c_st  = cnew;
        cb_st = cbarm;

        // ---- EARLY RELEASE: publish h + barrier arrive before the output tail ----
        g_hbuf[(iter + 1) & 1][q * HID + hb * HB2 + h] = hnew;
        BARS(bid);
        if (tl == 0) {
            __threadfence();
            unsigned old = atomicAdd(&g_cnt[sg], 1u);
            if (old == NARR - 1) {
                atomicExch(&g_cnt[sg], 0u);
                __threadfence();
                atomicAdd(&g_gen[sg], 1u);
            }
        }

        // ---- output tail (off the inter-CTA critical path) ----
        float hminus = go * ftanh_(cell);
        const int ob = (q * TQn + tq) * HID + hb * HB2 + h;
        out[0 * ARRN + ob] = cell;
        out[1 * ARRN + ob] = cbarm;
        out[2 * ARRN + ob] = gd;
        out[3 * ARRN + ob] = go;
        out[4 * ARRN + ob] = hnew;
        out[5 * ARRN + ob] = hminus;
    }
}

// ---------------- launch ----------------
extern "C" void kernel_launch(void* const* d_in, const int* in_sizes, int n_in,
                              void* d_out, int out_size) {
    const int*   ev    = (const int*)  d_in[0];
    const float* dtime = (const float*)d_in[1];
    const float* Emb   = (const float*)d_in[2];
    const float* W     = (const float*)d_in[3];
    const float* bias  = (const float*)d_in[4];
    float* out = (float*)d_out;

    ztab_kernel<<<35, 256>>>(Emb, W, bias);

    cudaFuncSetAttribute(scan_kernel,
                         cudaFuncAttributeMaxDynamicSharedMemorySize, SMEM_TOTAL);
    scan_kernel<<<128, 256, SMEM_TOTAL>>>(ev, dtime, W, out);
}